// round 11
// baseline (speedup 1.0000x reference)
#include <cuda_runtime.h>

#define NB 64
#define SEQLEN 512
#define HIDN 512
#define PROJ 128
#define NGATE 2048
typedef unsigned long long ull;

// ---------------- device scratch (no runtime allocation allowed) ------------
__device__ __align__(16) float g_A[NGATE * 16];       // fused input weights, row-padded to 16
__device__ __align__(16) float g_cbias[NGATE];
__device__ __align__(16) float g_cbase[NGATE * NB];   // [r][b]
__device__ __align__(16) float g_h[PROJ * NB];        // [p][b]
__device__ __align__(16) float g_ot[HIDN * NB];       // [k][b]
__device__ __align__(16) float g_xg[(size_t)SEQLEN * NGATE * NB]; // [t][r][b]
__device__ __align__(16) float g_hs[(size_t)SEQLEN * PROJ * NB];  // [t][p][b]
__device__ unsigned g_bar;

// ---------------- helpers ---------------------------------------------------
static __device__ __forceinline__ ull pk2(float x, float y) {
    ull r; asm("mov.b64 %0, {%1,%2};" : "=l"(r) : "f"(x), "f"(y)); return r;
}
static __device__ __forceinline__ void upk2(ull v, float& x, float& y) {
    asm("mov.b64 {%0,%1}, %2;" : "=f"(x), "=f"(y) : "l"(v));
}
static __device__ __forceinline__ ull ffma2(ull a, ull b, ull c) {
    ull d; asm("fma.rn.f32x2 %0, %1, %2, %3;" : "=l"(d) : "l"(a), "l"(b), "l"(c));
    return d;
}
static __device__ __forceinline__ float sigf(float x) {
    return __fdividef(1.f, 1.f + __expf(-x));
}
static __device__ __forceinline__ float tanh_fast(float x) {
    return 1.f - __fdividef(2.f, __expf(2.f * x) + 1.f);
}

// ---------------- grid barrier (monotonic counter, per-launch reset) ---------
static __device__ __forceinline__ void gbar(unsigned tgt) {
    __threadfence();
    __syncthreads();
    if (threadIdx.x == 0) {
        asm volatile("red.release.gpu.global.add.u32 [%0], 1;" :: "l"(&g_bar) : "memory");
        unsigned v;
        do {
            asm volatile("ld.acquire.gpu.global.u32 %0, [%1];" : "=r"(v) : "l"(&g_bar) : "memory");
        } while (v < tgt);
    }
    __syncthreads();
}

// ============================================================================
// S1: A[r][0..13], cbias[r]. 64 blocks x 1024 thr; one warp per gate row.
// Also resets the grid-barrier counter (runs before k_rec every launch/replay).
// ============================================================================
__global__ void k_setup1(const float* __restrict__ Wih,
                         const float* __restrict__ cmdW, const float* __restrict__ cmdb,
                         const float* __restrict__ coordW, const float* __restrict__ coordb,
                         const float* __restrict__ bih, const float* __restrict__ bhh) {
    if (blockIdx.x == 0 && threadIdx.x == 0) g_bar = 0u;
    int r = blockIdx.x * 32 + (threadIdx.x >> 5);
    int lane = threadIdx.x & 31;
    float acc[15];
#pragma unroll
    for (int j = 0; j < 15; j++) acc[j] = 0.f;
    for (int k = lane; k < HIDN; k += 32) {
        float w = Wih[(size_t)r * 768 + k];
#pragma unroll
        for (int j = 0; j < 6; j++) acc[j] += w * cmdW[k * 6 + j];
#pragma unroll
        for (int j = 0; j < 8; j++) acc[6 + j] += w * coordW[k * 8 + j];
        acc[14] += w * (cmdb[k] + coordb[k]);
    }
#pragma unroll
    for (int j = 0; j < 15; j++)
#pragma unroll
        for (int off = 16; off; off >>= 1)
            acc[j] += __shfl_down_sync(0xffffffffu, acc[j], off);
    if (lane == 0) {
#pragma unroll
        for (int j = 0; j < 14; j++) g_A[r * 16 + j] = acc[j];
        g_A[r * 16 + 14] = 0.f;
        g_A[r * 16 + 15] = 0.f;
        g_cbias[r] = acc[14] + bih[r] + bhh[r];
    }
}

// ============================================================================
// S2: cbase[r][b] = cbias[r] + W_ih_ctx[r]·ctx[b]; zero g_h. 16 blocks x 256.
// ============================================================================
__global__ void k_setup2(const float* __restrict__ Wih, const float* __restrict__ ctx) {
    __shared__ float sC[1024];
    int tid = threadIdx.x;
    if (blockIdx.x == 0)
        for (int i = tid; i < PROJ * NB; i += 256) g_h[i] = 0.f;
    int bs = blockIdx.x * 4;
    for (int i = tid; i < 1024; i += 256) sC[i] = ctx[(size_t)bs * 256 + i];
    __syncthreads();
    for (int r = tid; r < NGATE; r += 256) {
        float a0 = 0.f, a1 = 0.f, a2 = 0.f, a3 = 0.f;
        const float* wr = Wih + (size_t)r * 768 + 512;
        for (int l = 0; l < 256; l++) {
            float w = wr[l];
            a0 += w * sC[l]; a1 += w * sC[256 + l];
            a2 += w * sC[512 + l]; a3 += w * sC[768 + l];
        }
        float cb = g_cbias[r];
        g_cbase[r * 64 + bs + 0] = a0 + cb;
        g_cbase[r * 64 + bs + 1] = a1 + cb;
        g_cbase[r * 64 + bs + 2] = a2 + cb;
        g_cbase[r * 64 + bs + 3] = a3 + cb;
    }
}

// ============================================================================
// XG: x_gates[t][r][b] = cbase[r][b] + A[r]·x[b][t]. grid (512,32) x 256 thr.
// ============================================================================
__global__ void k_xg(const float* __restrict__ x) {
    __shared__ float xs[64 * 16];
    int t = blockIdx.x;
    int rbase = blockIdx.y * 64;
    int tid = threadIdx.x;
    for (int i = tid; i < 64 * 14; i += 256) {
        int b = i / 14, j = i % 14;
        xs[b * 16 + j] = x[((size_t)b * SEQLEN + t) * 14 + j];
    }
    __syncthreads();
    int rl = tid >> 2, bq = tid & 3;
    int r = rbase + rl;
    const float* Ar = g_A + r * 16;
    float a[14];
#pragma unroll
    for (int j = 0; j < 14; j++) a[j] = Ar[j];
    const float* cb = g_cbase + r * 64 + bq * 16;
    float* outp = g_xg + ((size_t)t * NGATE + r) * 64 + bq * 16;
#pragma unroll
    for (int q = 0; q < 4; q++) {
        float4 res;
        float* rp = (float*)&res;
#pragma unroll
        for (int e = 0; e < 4; e++) {
            int b = bq * 16 + q * 4 + e;
            float acc = cb[q * 4 + e];
            const float* xr = xs + b * 16;
#pragma unroll
            for (int j = 0; j < 14; j++) acc += a[j] * xr[j];
            rp[e] = acc;
        }
        *(float4*)(outp + q * 4) = res;
    }
}

// ============================================================================
// REC: persistent weight-stationary LSTM. 128 CTAs x 128 thr.
// Static smem = 49152 B exactly: sW 8K | sWr 8K | shh 32K (sg aliased into shh;
// temporally disjoint, guarded by __syncthreads).
// ============================================================================
__global__ void __launch_bounds__(128, 1)
k_rec(const float* __restrict__ Whh, const float* __restrict__ Whr) {
    __shared__ float sW[2048];
    __shared__ float sWr[2048];
    __shared__ float shh[8192];
    float* sg = shh;   // alias: used only after all shh reads of the phase
    const int tid = threadIdx.x;
    const int ci = blockIdx.x;
    const int k0 = ci * 4;

    // W_hh slice: 16 gate rows (i,f,g,o x 4 hidden units), coalesced rows
    for (int i = tid; i < 2048; i += 128) {
        int l = i >> 7, p = i & 127;
        int rg = (l >> 2) * 512 + k0 + (l & 3);
        sW[i] = Whh[(size_t)rg * 128 + p];
    }
    // W_hr slice, interleaved pairs for f32x2: [k][4] = {p0, p0+2, p0+1, p0+3}
    if (ci < 32) {
        int p0 = ci * 4;
        for (int i = tid; i < 2048; i += 128) {
            int k = i >> 2, j = i & 3;
            int p = p0 + ((j & 1) << 1) + (j >> 1);
            sWr[i] = Whr[(size_t)p * 512 + k];
        }
    }
    const int lr = tid >> 3;             // local gate row 0..15 (= gate*4 + unit)
    const int bb = (tid & 7) * 8;        // batch group
    const int rg_my = (lr >> 2) * 512 + k0 + (lr & 3);
    const int k1 = tid >> 6, b1 = tid & 63;          // cell slot 1 (units 0,1)
    const int k2 = (tid + 128) >> 6, b2 = tid & 63;  // cell slot 2 (units 2,3)
    float c0 = 0.f, c1 = 0.f;
    unsigned tgt = 0;
    __syncthreads();

    for (int t = 0; t < SEQLEN; t++) {
        // prefetch xg for this thread's row/batches (independent of h)
        const float* xgp = g_xg + ((size_t)t * NGATE + rg_my) * 64 + bb;
        ulonglong2 xa = *(const ulonglong2*)xgp;
        ulonglong2 xb = *(const ulonglong2*)(xgp + 4);
        // stage h[t-1] from L2 (L1 bypass: other CTAs wrote it)
        {
            const float4* src = (const float4*)g_h;
            float4* dst = (float4*)shh;
#pragma unroll
            for (int i = 0; i < 16; i++) dst[tid + i * 128] = __ldcg(src + tid + i * 128);
        }
        __syncthreads();
        // gates: 1 row x 8 batches per thread, K = 128, packed f32x2
        ull a0 = xa.x, a1 = xa.y, a2 = xb.x, a3 = xb.y;
        {
            const float* wrow = sW + lr * 128;
#pragma unroll 4
            for (int p = 0; p < 128; p++) {
                float w = wrow[p];
                ull ww = pk2(w, w);
                ulonglong2 ha = *(const ulonglong2*)(shh + p * 64 + bb);
                ulonglong2 hb = *(const ulonglong2*)(shh + p * 64 + bb + 4);
                a0 = ffma2(ww, ha.x, a0);
                a1 = ffma2(ww, ha.y, a1);
                a2 = ffma2(ww, hb.x, a2);
                a3 = ffma2(ww, hb.y, a3);
            }
        }
        // sg aliases shh: wait for ALL threads' gate-loop shh reads to finish
        __syncthreads();
        // exchange raw gates through smem
        {
            ulonglong2* d = (ulonglong2*)(sg + lr * 64 + bb);
            d[0] = make_ulonglong2(a0, a1);
            d[1] = make_ulonglong2(a2, a3);
        }
        __syncthreads();
        // cell update: 2 (unit, batch) slots per thread
        {
            float iv = sigf(sg[k1 * 64 + b1]);
            float fv = sigf(sg[(4 + k1) * 64 + b1]);
            float gv = tanh_fast(sg[(8 + k1) * 64 + b1]);
            float ov = sigf(sg[(12 + k1) * 64 + b1]);
            c0 = fv * c0 + iv * gv;
            g_ot[(k0 + k1) * 64 + b1] = ov * tanh_fast(c0);

            iv = sigf(sg[k2 * 64 + b2]);
            fv = sigf(sg[(4 + k2) * 64 + b2]);
            gv = tanh_fast(sg[(8 + k2) * 64 + b2]);
            ov = sigf(sg[(12 + k2) * 64 + b2]);
            c1 = fv * c1 + iv * gv;
            g_ot[(k0 + k2) * 64 + b2] = ov * tanh_fast(c1);
        }
        tgt += 128; gbar(tgt);

        // projection: CTAs 0..31, 4 p-rows each, K=512 split across thread halves
        if (ci < 32) {
            const int b = tid & 63;
            const int half = tid >> 6;
            ull accA = 0, accB = 0;  // bit pattern of (0.f, 0.f)
            for (int cch = 0; cch < 4; cch++) {
                const float4* src = (const float4*)(g_ot + cch * 8192);
                float4* dst = (float4*)shh;
#pragma unroll
                for (int i = 0; i < 16; i++) dst[tid + i * 128] = __ldcg(src + tid + i * 128);
                __syncthreads();
                const int kkb = half * 64;
#pragma unroll 4
                for (int kk = 0; kk < 64; kk++) {
                    int kl = kkb + kk;
                    float ov = shh[kl * 64 + b];
                    ull ovv = pk2(ov, ov);
                    ulonglong2 wp = *(const ulonglong2*)(sWr + (cch * 128 + kl) * 4);
                    accA = ffma2(ovv, wp.x, accA);
                    accB = ffma2(ovv, wp.y, accB);
                }
                __syncthreads();   // also guards the aliased sg write below
            }
            ((ulonglong2*)sg)[tid] = make_ulonglong2(accA, accB);
            __syncthreads();
            if (tid < 64) {
                ulonglong2 mine = ((ulonglong2*)sg)[tid];
                ulonglong2 oth  = ((ulonglong2*)sg)[tid + 64];
                float va0, va2, vb1, vb3, oa0, oa2, ob1, ob3;
                upk2(mine.x, va0, va2); upk2(mine.y, vb1, vb3);
                upk2(oth.x,  oa0, oa2); upk2(oth.y,  ob1, ob3);
                float v[4] = { va0 + oa0, vb1 + ob1, va2 + oa2, vb3 + ob3 };
                int p0 = ci * 4;
#pragma unroll
                for (int j = 0; j < 4; j++) {
                    float hv = v[j];
                    g_h[(p0 + j) * 64 + tid] = hv;
                    g_hs[((size_t)t * PROJ + p0 + j) * 64 + tid] = hv;
                }
            }
        }
        tgt += 128; gbar(tgt);
    }
}

// ============================================================================
// HEAD: LayerNorm + two output heads. 512 blocks (per t) x 64 thr (per b).
// ============================================================================
__global__ void k_head(const float* __restrict__ lng, const float* __restrict__ lnb,
                       const float* __restrict__ ocW, const float* __restrict__ ocb,
                       const float* __restrict__ oxW, const float* __restrict__ oxb,
                       const float* __restrict__ cscale, float* __restrict__ out) {
    __shared__ float sy[8192];
    __shared__ float s_ocW[768], s_oxW[804], s_lng[128], s_lnb[128], s_ocb[6], s_oxb[6], s_sc;
    int t = blockIdx.x, tid = threadIdx.x;
    {
        const float4* src = (const float4*)(g_hs + (size_t)t * 8192);
        float4* dst = (float4*)sy;
#pragma unroll
        for (int i = 0; i < 32; i++) dst[tid + i * 64] = src[tid + i * 64];
    }
    for (int i = tid; i < 768; i += 64) s_ocW[i] = ocW[i];
    for (int i = tid; i < 804; i += 64) s_oxW[i] = oxW[i];
    for (int i = tid; i < 128; i += 64) { s_lng[i] = lng[i]; s_lnb[i] = lnb[i]; }
    if (tid < 6) { s_ocb[tid] = ocb[tid]; s_oxb[tid] = oxb[tid]; }
    if (tid == 0) s_sc = cscale[0];
    __syncthreads();
    int b = tid;
    float sum = 0.f, sq = 0.f;
    for (int p = 0; p < 128; p++) { float v = sy[p * 64 + b]; sum += v; sq += v * v; }
    float mu = sum * (1.f / 128.f);
    float var = sq * (1.f / 128.f) - mu * mu;
    float rs = rsqrtf(var + 1e-5f);
    float cl[6], cx[6];
#pragma unroll
    for (int j = 0; j < 6; j++) { cl[j] = s_ocb[j]; cx[j] = s_oxb[j]; }
    for (int p = 0; p < 128; p++) {
        float y = (sy[p * 64 + b] - mu) * rs * s_lng[p] + s_lnb[p];
#pragma unroll
        for (int j = 0; j < 6; j++) cl[j] += y * s_ocW[j * 128 + p];
#pragma unroll
        for (int j = 0; j < 6; j++) cx[j] += y * s_oxW[j * 134 + p];
    }
#pragma unroll
    for (int j = 0; j < 6; j++)
#pragma unroll
        for (int m = 0; m < 6; m++) cx[j] += cl[m] * s_oxW[j * 134 + 128 + m];
    size_t o1 = ((size_t)b * SEQLEN + t) * 6;
#pragma unroll
    for (int j = 0; j < 6; j++) {
        out[o1 + j] = cl[j];
        out[196608 + o1 + j] = tanh_fast(cx[j] * s_sc);
    }
}

// ============================================================================
extern "C" void kernel_launch(void* const* d_in, const int* in_sizes, int n_in,
                              void* d_out, int out_size) {
    const float* x      = (const float*)d_in[0];
    const float* ctx    = (const float*)d_in[1];
    const float* cmdW   = (const float*)d_in[2];
    const float* cmdb   = (const float*)d_in[3];
    const float* coordW = (const float*)d_in[4];
    const float* coordb = (const float*)d_in[5];
    const float* Wih    = (const float*)d_in[6];
    const float* Whh    = (const float*)d_in[7];
    const float* bih    = (const float*)d_in[8];
    const float* bhh    = (const float*)d_in[9];
    const float* Whr    = (const float*)d_in[10];
    const float* lng    = (const float*)d_in[11];
    const float* lnb    = (const float*)d_in[12];
    const float* ocW    = (const float*)d_in[13];
    const float* ocb    = (const float*)d_in[14];
    const float* oxW    = (const float*)d_in[15];
    const float* oxb    = (const float*)d_in[16];
    const float* csc    = (const float*)d_in[17];
    float* out = (float*)d_out;

    k_setup1<<<64, 1024>>>(Wih, cmdW, cmdb, coordW, coordb, bih, bhh);
    k_setup2<<<16, 256>>>(Wih, ctx);
    k_xg<<<dim3(512, 32), 256>>>(x);
    k_rec<<<128, 128>>>(Whh, Whr);
    k_head<<<512, 64>>>(lng, lnb, ocW, ocb, oxW, oxb, csc, out);
}

// round 12
// speedup vs baseline: 1.8255x; 1.8255x over previous
#include <cuda_runtime.h>

#define NB 64
#define SEQLEN 512
#define HIDN 512
#define PROJ 128
#define NGATE 2048
#define G 8        // CTAs per group
#define NGRP 16    // groups (16*8 = 128 CTAs, 4 batches per group)
typedef unsigned long long ull;

// ---------------- device scratch (no runtime allocation allowed) ------------
__device__ __align__(16) float g_A[NGATE * 16];
__device__ __align__(16) float g_cbias[NGATE];
__device__ __align__(16) float g_cbase[NGATE * NB];                 // [r][b]
__device__ __align__(16) float g_h2[NGRP * PROJ * 4];               // [gr][p][b4]
__device__ __align__(16) float g_z[NGRP * HIDN * 4];                // [gr][k][b4]
__device__ __align__(16) float g_xg2[(size_t)SEQLEN * 128 * 1024];  // [t][ci][rr*4+b']
__device__ __align__(16) float g_hs[(size_t)SEQLEN * PROJ * NB];    // [t][p][b]
__device__ unsigned g_barG[NGRP * 32];                              // 128B-spaced counters

// ---------------- helpers ---------------------------------------------------
static __device__ __forceinline__ ull pk2(float x, float y) {
    ull r; asm("mov.b64 %0, {%1,%2};" : "=l"(r) : "f"(x), "f"(y)); return r;
}
static __device__ __forceinline__ void upk2(ull v, float& x, float& y) {
    asm("mov.b64 {%0,%1}, %2;" : "=f"(x), "=f"(y) : "l"(v));
}
static __device__ __forceinline__ ull ffma2(ull a, ull b, ull c) {
    ull d; asm("fma.rn.f32x2 %0, %1, %2, %3;" : "=l"(d) : "l"(a), "l"(b), "l"(c));
    return d;
}
static __device__ __forceinline__ float sigf(float x) {
    return __fdividef(1.f, 1.f + __expf(-x));
}
static __device__ __forceinline__ float tanh_fast(float x) {
    return 1.f - __fdividef(2.f, __expf(2.f * x) + 1.f);
}

// group barrier: 8 arrivals on a group-private counter; thread-0-only fence
// (bar.sync orders CTA stores at CTA scope; thread 0's membar.gl promotes to
// gpu scope via fence cumulativity before the release-add).
static __device__ __forceinline__ void gbarG(unsigned* bar, unsigned tgt) {
    __syncthreads();
    if (threadIdx.x == 0) {
        __threadfence();
        asm volatile("red.release.gpu.global.add.u32 [%0], 1;" :: "l"(bar) : "memory");
        unsigned v;
        do {
            asm volatile("ld.acquire.gpu.global.u32 %0, [%1];" : "=r"(v) : "l"(bar) : "memory");
        } while (v < tgt);
    }
    __syncthreads();
}

// ============================================================================
// S1: A[r][0..13], cbias[r]. 64 blocks x 1024 thr; one warp per gate row.
// Also resets all group-barrier counters.
// ============================================================================
__global__ void k_setup1(const float* __restrict__ Wih,
                         const float* __restrict__ cmdW, const float* __restrict__ cmdb,
                         const float* __restrict__ coordW, const float* __restrict__ coordb,
                         const float* __restrict__ bih, const float* __restrict__ bhh) {
    if (blockIdx.x == 0 && threadIdx.x < NGRP * 32) g_barG[threadIdx.x] = 0u;
    int r = blockIdx.x * 32 + (threadIdx.x >> 5);
    int lane = threadIdx.x & 31;
    float acc[15];
#pragma unroll
    for (int j = 0; j < 15; j++) acc[j] = 0.f;
    for (int k = lane; k < HIDN; k += 32) {
        float w = Wih[(size_t)r * 768 + k];
#pragma unroll
        for (int j = 0; j < 6; j++) acc[j] += w * cmdW[k * 6 + j];
#pragma unroll
        for (int j = 0; j < 8; j++) acc[6 + j] += w * coordW[k * 8 + j];
        acc[14] += w * (cmdb[k] + coordb[k]);
    }
#pragma unroll
    for (int j = 0; j < 15; j++)
#pragma unroll
        for (int off = 16; off; off >>= 1)
            acc[j] += __shfl_down_sync(0xffffffffu, acc[j], off);
    if (lane == 0) {
#pragma unroll
        for (int j = 0; j < 14; j++) g_A[r * 16 + j] = acc[j];
        g_A[r * 16 + 14] = 0.f;
        g_A[r * 16 + 15] = 0.f;
        g_cbias[r] = acc[14] + bih[r] + bhh[r];
    }
}

// ============================================================================
// S2: cbase[r][b] = cbias[r] + W_ih_ctx[r]·ctx[b]; zero g_h2. 16 blocks x 256.
// ============================================================================
__global__ void k_setup2(const float* __restrict__ Wih, const float* __restrict__ ctx) {
    __shared__ float sC[1024];
    int tid = threadIdx.x;
    if (blockIdx.x == 0)
        for (int i = tid; i < NGRP * PROJ * 4; i += 256) g_h2[i] = 0.f;
    int bs = blockIdx.x * 4;
    for (int i = tid; i < 1024; i += 256) sC[i] = ctx[(size_t)bs * 256 + i];
    __syncthreads();
    for (int r = tid; r < NGATE; r += 256) {
        float a0 = 0.f, a1 = 0.f, a2 = 0.f, a3 = 0.f;
        const float* wr = Wih + (size_t)r * 768 + 512;
        for (int l = 0; l < 256; l++) {
            float w = wr[l];
            a0 += w * sC[l]; a1 += w * sC[256 + l];
            a2 += w * sC[512 + l]; a3 += w * sC[768 + l];
        }
        float cb = g_cbias[r];
        g_cbase[r * 64 + bs + 0] = a0 + cb;
        g_cbase[r * 64 + bs + 1] = a1 + cb;
        g_cbase[r * 64 + bs + 2] = a2 + cb;
        g_cbase[r * 64 + bs + 3] = a3 + cb;
    }
}

// ============================================================================
// XG: x_gates into per-CTA blocks: g_xg2[t][ci][(q*64+ul)*4 + b'] where the
// CTA ci = gr*8+cg owns rows {q*512+cg*64+ul} and batches {gr*4+b'}.
// grid (512,32) x 256 thr (same compute as before; only the store remaps).
// ============================================================================
__global__ void k_xg(const float* __restrict__ x) {
    __shared__ float xs[64 * 16];
    int t = blockIdx.x;
    int rbase = blockIdx.y * 64;
    int tid = threadIdx.x;
    for (int i = tid; i < 64 * 14; i += 256) {
        int b = i / 14, j = i % 14;
        xs[b * 16 + j] = x[((size_t)b * SEQLEN + t) * 14 + j];
    }
    __syncthreads();
    int rl = tid >> 2, bq = tid & 3;
    int r = rbase + rl;
    const float* Ar = g_A + r * 16;
    float a[14];
#pragma unroll
    for (int j = 0; j < 14; j++) a[j] = Ar[j];
    const float* cb = g_cbase + r * 64 + bq * 16;
    int qq = r >> 9, cgx = (r >> 6) & 7, ul = r & 63;
    int rr = qq * 64 + ul;   // local row index inside owning CTA
#pragma unroll
    for (int q = 0; q < 4; q++) {
        float4 res;
        float* rp = (float*)&res;
#pragma unroll
        for (int e = 0; e < 4; e++) {
            int b = bq * 16 + q * 4 + e;
            float acc = cb[q * 4 + e];
            const float* xr = xs + b * 16;
#pragma unroll
            for (int j = 0; j < 14; j++) acc += a[j] * xr[j];
            rp[e] = acc;
        }
        int gr = bq * 4 + q;   // batch-quad (bq*16+q*4..+4) = group gr, b'=e
        float4* outp = (float4*)(g_xg2 + (((size_t)t * 128 + gr * 8 + cgx) * 1024)) + rr;
        *outp = res;
    }
}

// ============================================================================
// REC: 16 independent groups x 8 CTAs x 4 batches. 128 CTAs x 128 thr.
// Dynamic smem 204288 B: sW[k128][rr256] 131072 | sWhr[16][520] 33280 |
// sH[k128][b4] 2048 | sGate[rr256][b4] 4096 | sZ[i128][kq4][b4] 32768 | sRed 1024
// ============================================================================
__global__ void __launch_bounds__(128, 1)
k_rec(const float* __restrict__ Whh, const float* __restrict__ Whr) {
    extern __shared__ float sm[];
    float* sW    = sm;                 // 32768 f
    float* sWhr  = sm + 32768;         // 8320 f
    float* sH    = sm + 41088;         // 512 f
    float* sGate = sm + 41600;         // 1024 f
    float* sZ    = sm + 42624;         // 8192 f
    float* sRed  = sm + 50816;         // 256 f (128 ull)
    const int tid = threadIdx.x;
    const int ci = blockIdx.x;
    const int gr = ci >> 3;
    const int cg = ci & 7;
    unsigned* bar = &g_barG[gr * 32];

    // W_hh shard: 256 gate rows (q*512 + cg*64 + ul), k-major in smem
    for (int i = tid; i < 32768; i += 128) {
        int rr = i >> 7, k = i & 127;
        int rglob = (rr >> 6) * 512 + cg * 64 + (rr & 63);
        sW[k * 256 + rr] = Whh[(size_t)rglob * 128 + k];
    }
    // W_hr shard: 16 p-rows (cg*16+pl), padded stride 520 (bank spread)
    for (int i = tid; i < 16 * 512; i += 128) {
        int pl = i >> 9, k = i & 511;
        sWhr[pl * 520 + k] = Whr[(size_t)(cg * 16 + pl) * 512 + k];
    }
    // phase A map: thread = (q = tid>>5, j = tid&31) -> rows 2tid, 2tid+1 (local)
    // cell map: slots s = 2tid, 2tid+1: u = s>>2, b = s&3 (b even pair)
    const int u1 = tid >> 1;
    const int bsl = (2 * tid) & 3;
    // phase B map: pl = tid>>3, bp = (tid>>2)&1, kq = tid&3
    const int pl = tid >> 3, bp = (tid >> 2) & 1, kq = tid & 3;
    float c0 = 0.f, c1 = 0.f;
    unsigned tgt = 0;
    __syncthreads();

    for (int t = 0; t < SEQLEN; t++) {
        // xg prefetch: float4 index rr = 2tid, 2tid+1
        const float4* xgp = (const float4*)(g_xg2 + ((size_t)t * 128 + ci) * 1024) + 2 * tid;
        float4 xg0 = __ldcg(xgp);
        float4 xg1 = __ldcg(xgp + 1);
        // stage h[t-1] for this group's 4 batches (2 KB)
        ((float4*)sH)[tid] = __ldcg((const float4*)(g_h2 + (size_t)gr * 512) + tid);
        __syncthreads();

        // gates: rows 2tid,2tid+1 x 4 batches, K=128
        ull a00 = pk2(xg0.x, xg0.y), a01 = pk2(xg0.z, xg0.w);
        ull a10 = pk2(xg1.x, xg1.y), a11 = pk2(xg1.z, xg1.w);
        {
            const float* wbase = sW + 2 * tid;
#pragma unroll 4
            for (int k = 0; k < 128; k++) {
                float2 w = *(const float2*)(wbase + k * 256);
                ulonglong2 hv = *(const ulonglong2*)(sH + k * 4);
                ull w0 = pk2(w.x, w.x), w1 = pk2(w.y, w.y);
                a00 = ffma2(w0, hv.x, a00); a01 = ffma2(w0, hv.y, a01);
                a10 = ffma2(w1, hv.x, a10); a11 = ffma2(w1, hv.y, a11);
            }
        }
        // exchange raw gates (sGate disjoint from sH)
        {
            float4 v0, v1;
            upk2(a00, v0.x, v0.y); upk2(a01, v0.z, v0.w);
            upk2(a10, v1.x, v1.y); upk2(a11, v1.z, v1.w);
            ((float4*)sGate)[2 * tid] = v0;
            ((float4*)sGate)[2 * tid + 1] = v1;
        }
        __syncthreads();
        // cell update: 2 slots (u1, bsl), (u1, bsl+1); gate q at row q*64+u
        {
            float i0 = sigf(sGate[(u1) * 4 + bsl]);
            float f0 = sigf(sGate[(64 + u1) * 4 + bsl]);
            float gg0 = tanh_fast(sGate[(128 + u1) * 4 + bsl]);
            float o0 = sigf(sGate[(192 + u1) * 4 + bsl]);
            c0 = f0 * c0 + i0 * gg0;
            float z0 = o0 * tanh_fast(c0);
            float i1 = sigf(sGate[(u1) * 4 + bsl + 1]);
            float f1 = sigf(sGate[(64 + u1) * 4 + bsl + 1]);
            float gg1 = tanh_fast(sGate[(128 + u1) * 4 + bsl + 1]);
            float o1 = sigf(sGate[(192 + u1) * 4 + bsl + 1]);
            c1 = f1 * c1 + i1 * gg1;
            float z1 = o1 * tanh_fast(c1);
            // z global row k = cg*64 + u1, batches bsl, bsl+1 (contiguous 8B)
            *(float2*)(g_z + (size_t)gr * 2048 + (cg * 64 + u1) * 4 + bsl) = make_float2(z0, z1);
        }
        tgt += G; gbarG(bar, tgt);

        // phase B: stage full group z (8 KB) with kq-interleaved layout
        {
            const float4* src = (const float4*)(g_z + (size_t)gr * 2048);
#pragma unroll
            for (int i2 = 0; i2 < 4; i2++) {
                int k = tid + i2 * 128;
                float4 v = __ldcg(src + k);
                ((float4*)sZ)[(k & 127) * 4 + (k >> 7)] = v;
            }
        }
        __syncthreads();
        // partial dot: p-row pl, batches (2bp,2bp+1), k in [kq*128, kq*128+128)
        ull acc = 0ull;
        {
            const float* wrow = sWhr + pl * 520 + kq * 128;
            const float* zcol = sZ + kq * 4 + bp * 2;
#pragma unroll 4
            for (int i2 = 0; i2 < 128; i2++) {
                float w = wrow[i2];
                float2 zv = *(const float2*)(zcol + i2 * 16);
                acc = ffma2(pk2(w, w), pk2(zv.x, zv.y), acc);
            }
        }
        ((ull*)sRed)[tid] = acc;
        __syncthreads();
        if (tid < 32) {
            int pl2 = tid >> 1, bp2 = tid & 1;
            const ull* rp = (const ull*)sRed + pl2 * 8 + bp2 * 4;
            float x0, y0, x1, y1, x2, y2, x3, y3;
            upk2(rp[0], x0, y0); upk2(rp[1], x1, y1);
            upk2(rp[2], x2, y2); upk2(rp[3], x3, y3);
            float h0 = x0 + x1 + x2 + x3, h1 = y0 + y1 + y2 + y3;
            int p = cg * 16 + pl2;
            *(float2*)(g_h2 + (size_t)gr * 512 + p * 4 + bp2 * 2) = make_float2(h0, h1);
            *(float2*)(g_hs + ((size_t)t * PROJ + p) * 64 + gr * 4 + bp2 * 2) = make_float2(h0, h1);
        }
        tgt += G; gbarG(bar, tgt);
    }
}

// ============================================================================
// HEAD: LayerNorm + two output heads. 512 blocks (per t) x 64 thr (per b).
// ============================================================================
__global__ void k_head(const float* __restrict__ lng, const float* __restrict__ lnb,
                       const float* __restrict__ ocW, const float* __restrict__ ocb,
                       const float* __restrict__ oxW, const float* __restrict__ oxb,
                       const float* __restrict__ cscale, float* __restrict__ out) {
    __shared__ float sy[8192];
    __shared__ float s_ocW[768], s_oxW[804], s_lng[128], s_lnb[128], s_ocb[6], s_oxb[6], s_sc;
    int t = blockIdx.x, tid = threadIdx.x;
    {
        const float4* src = (const float4*)(g_hs + (size_t)t * 8192);
        float4* dst = (float4*)sy;
#pragma unroll
        for (int i = 0; i < 32; i++) dst[tid + i * 64] = src[tid + i * 64];
    }
    for (int i = tid; i < 768; i += 64) s_ocW[i] = ocW[i];
    for (int i = tid; i < 804; i += 64) s_oxW[i] = oxW[i];
    for (int i = tid; i < 128; i += 64) { s_lng[i] = lng[i]; s_lnb[i] = lnb[i]; }
    if (tid < 6) { s_ocb[tid] = ocb[tid]; s_oxb[tid] = oxb[tid]; }
    if (tid == 0) s_sc = cscale[0];
    __syncthreads();
    int b = tid;
    float sum = 0.f, sq = 0.f;
    for (int p = 0; p < 128; p++) { float v = sy[p * 64 + b]; sum += v; sq += v * v; }
    float mu = sum * (1.f / 128.f);
    float var = sq * (1.f / 128.f) - mu * mu;
    float rs = rsqrtf(var + 1e-5f);
    float cl[6], cx[6];
#pragma unroll
    for (int j = 0; j < 6; j++) { cl[j] = s_ocb[j]; cx[j] = s_oxb[j]; }
    for (int p = 0; p < 128; p++) {
        float y = (sy[p * 64 + b] - mu) * rs * s_lng[p] + s_lnb[p];
#pragma unroll
        for (int j = 0; j < 6; j++) cl[j] += y * s_ocW[j * 128 + p];
#pragma unroll
        for (int j = 0; j < 6; j++) cx[j] += y * s_oxW[j * 134 + p];
    }
#pragma unroll
    for (int j = 0; j < 6; j++)
#pragma unroll
        for (int m = 0; m < 6; m++) cx[j] += cl[m] * s_oxW[j * 134 + 128 + m];
    size_t o1 = ((size_t)b * SEQLEN + t) * 6;
#pragma unroll
    for (int j = 0; j < 6; j++) {
        out[o1 + j] = cl[j];
        out[196608 + o1 + j] = tanh_fast(cx[j] * s_sc);
    }
}

// ============================================================================
extern "C" void kernel_launch(void* const* d_in, const int* in_sizes, int n_in,
                              void* d_out, int out_size) {
    const float* x      = (const float*)d_in[0];
    const float* ctx    = (const float*)d_in[1];
    const float* cmdW   = (const float*)d_in[2];
    const float* cmdb   = (const float*)d_in[3];
    const float* coordW = (const float*)d_in[4];
    const float* coordb = (const float*)d_in[5];
    const float* Wih    = (const float*)d_in[6];
    const float* Whh    = (const float*)d_in[7];
    const float* bih    = (const float*)d_in[8];
    const float* bhh    = (const float*)d_in[9];
    const float* Whr    = (const float*)d_in[10];
    const float* lng    = (const float*)d_in[11];
    const float* lnb    = (const float*)d_in[12];
    const float* ocW    = (const float*)d_in[13];
    const float* ocb    = (const float*)d_in[14];
    const float* oxW    = (const float*)d_in[15];
    const float* oxb    = (const float*)d_in[16];
    const float* csc    = (const float*)d_in[17];
    float* out = (float*)d_out;

    // Unconditional, idempotent, capture-safe (not a stream op).
    cudaFuncSetAttribute(k_rec, cudaFuncAttributeMaxDynamicSharedMemorySize, 204288);

    k_setup1<<<64, 1024>>>(Wih, cmdW, cmdb, coordW, coordb, bih, bhh);
    k_setup2<<<16, 256>>>(Wih, ctx);
    k_xg<<<dim3(512, 32), 256>>>(x);
    k_rec<<<128, 128, 204288>>>(Whh, Whr);
    k_head<<<512, 64>>>(lng, lnb, ocW, ocb, oxW, oxb, csc, out);
}